// round 3
// baseline (speedup 1.0000x reference)
#include <cuda_runtime.h>

#define L 256
#define BB 16
#define LL2 (L * L)
#define TRI_TOTAL ((L * (L + 1)) / 2)   // 32896
#define NEGF (-1000000000.0f)
#define TMAIN 1024

// -------- device scratch (no allocations allowed) --------
__device__ float  g_betaS[BB * LL2];   // beta by start index:  betaS[i*L + w] = beta(i, i+w)
__device__ float  g_betaE[BB * LL2];   // beta by end index:    betaE[j*L + w] = beta(j-w, j)
__device__ float  g_lgT[BB * LL2];     // transposed span_logits: lgT[j*L + i] = lg[i*L + j]
__device__ int    g_lens[BB];
__device__ double g_acc[3];            // 0: span pos+neg log-sum, 1: ph BCE num, 2: pt BCE num

__device__ __forceinline__ int roff(int i) {
    // packed triangular row offset (row-major by span start)
    return i * L - ((i * (i - 1)) >> 1);
}

__device__ __forceinline__ void lse_add(float& m, float& s, float v) {
    float nm = fmaxf(m, v);
    s = s * __expf(m - nm) + __expf(v - nm);
    m = nm;
}

// -------- kernel 1: zero accumulators, compute lens (dtype-robust) --------
// maskspan[b, 0, j] = (j < lens[b]); lens[b] in [128, 256].
// If stored as uint8 bool: first-256-byte scan gives count in [128,256] and byte0==1.
// If stored as int32 (or float32): byte scan sees 64 (or 128 with byte0==0) -> re-read
// the row as 256 4-byte words and count nonzero words (correct for int32 AND float32).
__global__ void init_kernel(const unsigned char* __restrict__ maskspan) {
    int t = threadIdx.x;
    if (t < 3) g_acc[t] = 0.0;
    if (t < BB) {
        const unsigned char* rowb = maskspan + (size_t)t * LL2;  // assume 1 byte/elem
        int cnt8 = 0;
        for (int j = 0; j < L; ++j) cnt8 += (rowb[j] != 0) ? 1 : 0;
        int len;
        if (cnt8 >= 100 && rowb[0] == 1) {
            len = cnt8;
        } else {
            const unsigned int* rowi = ((const unsigned int*)maskspan) + (size_t)t * LL2;
            int cnt32 = 0;
            for (int j = 0; j < L; ++j) cnt32 += (rowi[j] != 0u) ? 1 : 0;
            len = cnt32;
        }
        if (len < 1) len = 1;
        if (len > L) len = L;
        g_lens[t] = len;
    }
}

// -------- kernel 2: inside + outside + span loss, one CTA per batch --------
__global__ void __launch_bounds__(TMAIN, 1)
chart_kernel(const float* __restrict__ lg_all,
             const float* __restrict__ ph_arc_all,
             const int* __restrict__ spans_all) {
    extern __shared__ float S[];          // TRI_TOTAL floats: beta chart, then reused as alpha chart
    __shared__ double sh_red[32];
    __shared__ float  sh_logZ;

    const int b = blockIdx.x;
    const int n = g_lens[b];
    const float* __restrict__ lg     = lg_all     + (size_t)b * LL2;
    const float* __restrict__ ph_arc = ph_arc_all + (size_t)b * LL2;
    const int*   __restrict__ spans  = spans_all  + (size_t)b * LL2;
    float* __restrict__ betaS = g_betaS + (size_t)b * LL2;
    float* __restrict__ betaE = g_betaE + (size_t)b * LL2;
    float* __restrict__ lgT   = g_lgT   + (size_t)b * LL2;

    const int tid  = threadIdx.x;
    const int lane = tid & 31;
    const int wid  = tid >> 5;

    // transpose lg for contiguous type-2 reads in outside pass
    for (int idx = tid; idx < LL2; idx += TMAIN) {
        int i = idx >> 8, j = idx & (L - 1);
        lgT[j * L + i] = lg[idx];
    }

    // ---- inside, width 0 ----
    for (int i = tid; i < n; i += TMAIN) {
        float v = lg[i * L + i];
        S[roff(i)]      = v;
        betaS[i * L]    = v;
        betaE[i * L]    = v;
    }
    __syncthreads();

    // ---- inside, widths 1..n-1 ----
    for (int w = 1; w < n; ++w) {
        const int ncells = n - w;
        if (w <= 32) {
            // thread per cell, serial over splits
            for (int i = tid; i < ncells; i += TMAIN) {
                const int baseL = roff(i);
                float m = NEGF, s = 0.f;
                for (int d = 0; d < w; ++d) {
                    int r = i + d + 1;
                    lse_add(m, s, S[baseL + d] + S[roff(r) + (w - 1 - d)]);
                }
                float res = m + __logf(s) + lg[i * L + i + w];
                S[baseL + w]           = res;
                betaS[i * L + w]       = res;
                betaE[(i + w) * L + w] = res;
            }
        } else {
            // warp per cell, lanes over splits
            for (int i = wid; i < ncells; i += 32) {
                const int baseL = roff(i);
                float m = NEGF, s = 0.f;
                for (int d = lane; d < w; d += 32) {
                    int r = i + d + 1;
                    lse_add(m, s, S[baseL + d] + S[roff(r) + (w - 1 - d)]);
                }
                #pragma unroll
                for (int off = 16; off; off >>= 1) {
                    float om = __shfl_xor_sync(0xffffffffu, m, off);
                    float os = __shfl_xor_sync(0xffffffffu, s, off);
                    float nm = fmaxf(m, om);
                    s = s * __expf(m - nm) + os * __expf(om - nm);
                    m = nm;
                }
                if (lane == 0) {
                    float res = m + __logf(s) + lg[i * L + i + w];
                    S[baseL + w]           = res;
                    betaS[i * L + w]       = res;
                    betaE[(i + w) * L + w] = res;
                }
            }
        }
        __syncthreads();
    }

    if (tid == 0) sh_logZ = S[roff(0) + (n - 1)];
    __syncthreads();
    const float logZ = sh_logZ;

    // ---- re-init chart as alpha ----
    for (int idx = tid; idx < TRI_TOTAL; idx += TMAIN) S[idx] = NEGF;
    __syncthreads();
    if (tid == 0) S[roff(0) + (n - 1)] = 0.f;   // root
    __syncthreads();

    double acc = 0.0;

    // ---- outside, widths n-1..0 (loss fused) ----
    for (int w = n - 1; w >= 0; --w) {
        const int ncells = n - w;
        const int T = n - 1 - w;          // parent terms per cell (uniform at a given width)
        if (T <= 32) {
            for (int a = tid; a < ncells; a += TMAIN) {
                const int bj = a + w;
                const int c1 = n - 1 - bj;
                float m = NEGF, s = 0.f;
                const float* aS  = S + roff(a) + w + 1;       // alpha[a][bj+1+t]
                const float* lg1 = lg + a * L + bj + 1;       // lg[a][bj+1+t]
                const float* bS  = betaS + (bj + 1) * L;      // beta[bj+1][width t]
                for (int t = 0; t < c1; ++t)
                    lse_add(m, s, aS[t] + lg1[t] + bS[t]);
                const float* lg2 = lgT + bj * L;              // lg[ii][bj]
                const float* bE  = betaE + (a - 1) * L + (a - 1); // beta[ii..a-1], end a-1
                for (int ii = 0; ii < a; ++ii)
                    lse_add(m, s, S[roff(ii) + (bj - ii)] + lg2[ii] + bE[-ii]);
                float alpha_v = (T > 0) ? (m + __logf(s)) : 0.f;
                S[roff(a) + w] = alpha_v;
                float mu = __expf(alpha_v + betaS[a * L + w] - logZ);
                mu = fminf(mu, 1.0f);
                float p  = 1.f / (1.f + __expf(-ph_arc[a * L + bj]));
                float pm = p * mu;
                acc += (spans[a * L + bj] >= 2) ? (double)logf(pm) : (double)log1pf(-pm);
            }
        } else {
            for (int a = wid; a < ncells; a += 32) {
                const int bj = a + w;
                const int c1 = n - 1 - bj;
                float m = NEGF, s = 0.f;
                const float* aS  = S + roff(a) + w + 1;
                const float* lg1 = lg + a * L + bj + 1;
                const float* bS  = betaS + (bj + 1) * L;
                for (int t = lane; t < c1; t += 32)
                    lse_add(m, s, aS[t] + lg1[t] + bS[t]);
                const float* lg2 = lgT + bj * L;
                const float* bE  = betaE + (a - 1) * L + (a - 1);
                for (int ii = lane; ii < a; ii += 32)
                    lse_add(m, s, S[roff(ii) + (bj - ii)] + lg2[ii] + bE[-ii]);
                #pragma unroll
                for (int off = 16; off; off >>= 1) {
                    float om = __shfl_xor_sync(0xffffffffu, m, off);
                    float os = __shfl_xor_sync(0xffffffffu, s, off);
                    float nm = fmaxf(m, om);
                    s = s * __expf(m - nm) + os * __expf(om - nm);
                    m = nm;
                }
                if (lane == 0) {
                    float alpha_v = m + __logf(s);
                    S[roff(a) + w] = alpha_v;
                    float mu = __expf(alpha_v + betaS[a * L + w] - logZ);
                    mu = fminf(mu, 1.0f);
                    float p  = 1.f / (1.f + __expf(-ph_arc[a * L + bj]));
                    float pm = p * mu;
                    acc += (spans[a * L + bj] >= 2) ? (double)logf(pm) : (double)log1pf(-pm);
                }
            }
        }
        __syncthreads();
    }

    // ---- block-reduce span loss, one atomic per CTA ----
    #pragma unroll
    for (int off = 16; off; off >>= 1)
        acc += __shfl_down_sync(0xffffffffu, acc, off);
    if (lane == 0) sh_red[wid] = acc;
    __syncthreads();
    if (wid == 0) {
        double v = sh_red[lane];
        #pragma unroll
        for (int off = 16; off; off >>= 1)
            v += __shfl_down_sync(0xffffffffu, v, off);
        if (lane == 0) atomicAdd(&g_acc[0], v);
    }
}

// -------- kernel 3: BCE reductions for ph / pt --------
__global__ void bce_kernel(const float* __restrict__ ph, const float* __restrict__ pt,
                           const int* __restrict__ ph_ind, const int* __restrict__ pt_ind) {
    __shared__ double shp[8], sht[8];
    double a1 = 0.0, a2 = 0.0;
    const int total  = BB * LL2;
    const int stride = gridDim.x * blockDim.x;
    for (int idx = blockIdx.x * blockDim.x + threadIdx.x; idx < total; idx += stride) {
        int bb = idx >> 16;
        int n  = g_lens[bb];
        int i  = (idx >> 8) & (L - 1);
        int j  = idx & (L - 1);
        if (i < n && j < n) {
            float x = ph[idx];
            a1 += (double)(fmaxf(x, 0.f) + log1pf(__expf(-fabsf(x))) - x * (float)ph_ind[idx]);
            float y = pt[idx];
            a2 += (double)(fmaxf(y, 0.f) + log1pf(__expf(-fabsf(y))) - y * (float)pt_ind[idx]);
        }
    }
    #pragma unroll
    for (int off = 16; off; off >>= 1) {
        a1 += __shfl_down_sync(0xffffffffu, a1, off);
        a2 += __shfl_down_sync(0xffffffffu, a2, off);
    }
    int lane = threadIdx.x & 31, wd = threadIdx.x >> 5;
    if (lane == 0) { shp[wd] = a1; sht[wd] = a2; }
    __syncthreads();
    if (threadIdx.x == 0) {
        double s1 = 0.0, s2 = 0.0;
        int nw = (int)(blockDim.x >> 5);
        for (int k = 0; k < nw; ++k) { s1 += shp[k]; s2 += sht[k]; }
        atomicAdd(&g_acc[1], s1);
        atomicAdd(&g_acc[2], s2);
    }
}

// -------- kernel 4: finalize --------
__global__ void final_kernel(float* __restrict__ out) {
    double lens_sum = 0.0, sq = 0.0;
    for (int bb = 0; bb < BB; ++bb) {
        double nn = (double)g_lens[bb];
        lens_sum += nn;
        sq += nn * nn;
    }
    double loss_spans = -(g_acc[0]) / lens_sum;
    double loss = 0.1 * loss_spans + 0.9 * (g_acc[1] / sq + g_acc[2] / sq);
    out[0] = (float)loss;
}

extern "C" void kernel_launch(void* const* d_in, const int* in_sizes, int n_in,
                              void* d_out, int out_size) {
    const float* span_logits = (const float*)d_in[0];
    const float* ph          = (const float*)d_in[1];
    const float* pt          = (const float*)d_in[2];
    const float* ph_arc      = (const float*)d_in[3];
    const int*   spans_ind   = (const int*)d_in[4];
    const int*   ph_ind      = (const int*)d_in[5];
    const int*   pt_ind      = (const int*)d_in[6];
    // d_in[7] = maskarc (unused; derived from lens), d_in[8] = maskspan
    const unsigned char* maskspan = (const unsigned char*)d_in[8];

    (void)in_sizes; (void)n_in; (void)out_size;

    cudaFuncSetAttribute(chart_kernel, cudaFuncAttributeMaxDynamicSharedMemorySize,
                         TRI_TOTAL * (int)sizeof(float));

    init_kernel<<<1, 64>>>(maskspan);
    chart_kernel<<<BB, TMAIN, TRI_TOTAL * sizeof(float)>>>(span_logits, ph_arc, spans_ind);
    bce_kernel<<<512, 256>>>(ph, pt, ph_ind, pt_ind);
    final_kernel<<<1, 1>>>((float*)d_out);
}

// round 4
// speedup vs baseline: 1.7213x; 1.7213x over previous
#include <cuda_runtime.h>

#define L 256
#define BB 16
#define NC 8                 // CTAs per cluster (= per batch)
#define LL2 (L * L)
#define NEGF (-1000000000.0f)
#define TMAIN 1024
#define WT 6000              // lane-term threshold: partitioned vs redundant level

// -------- device scratch (no allocations allowed) --------
__device__ float  g_bS[BB * LL2];   // beta start-major:  bS[i*L + w] = beta(i, i+w)
__device__ float  g_bE[BB * LL2];   // beta end-major:    bE[j*L + w] = beta(j-w, j)
__device__ float  g_aS[BB * LL2];   // alpha start-major: aS[a*L + w] = alpha(a, a+w)
__device__ float  g_aE[BB * LL2];   // alpha end-major:   aE[b*L + w] = alpha(b-w, b)
__device__ float  g_lgT[BB * LL2];  // lgT[j*L + i] = lg[i*L + j]
__device__ int    g_lens[BB];
__device__ double g_acc[3];         // 0: span log-sum, 1: ph BCE, 2: pt BCE

#define CLUSTER_SYNC() do { \
    asm volatile("barrier.cluster.arrive.aligned;" ::: "memory"); \
    asm volatile("barrier.cluster.wait.aligned;"   ::: "memory"); } while (0)

__device__ __forceinline__ void lse_add(float& m, float& s, float v) {
    float nm = fmaxf(m, v);
    s = s * __expf(m - nm) + __expf(v - nm);
    m = nm;
}

// merge per-lane (m,s) across the warp -> (M, S) valid in all lanes
__device__ __forceinline__ void warp_lse_merge(float m, float s, float& M, float& S) {
    M = m;
    #pragma unroll
    for (int o = 16; o; o >>= 1) M = fmaxf(M, __shfl_xor_sync(0xffffffffu, M, o));
    float sa = s * __expf(m - M);     // m==NEGF,s==0 lanes contribute 0
    #pragma unroll
    for (int o = 16; o; o >>= 1) sa += __shfl_xor_sync(0xffffffffu, sa, o);
    S = sa;
}

// -------- inside: one warp computes cell (i, i+w) --------
__device__ __forceinline__ void inside_cell(int i, int w, const float* __restrict__ lg,
                                            float* __restrict__ bS, float* __restrict__ bE,
                                            int lane) {
    const float* __restrict__ Lp = bS + i * L;          // widths 0..w-1, ascending
    const float* __restrict__ Rp = bE + (i + w) * L;    // index w-1-t, descending
    float m = NEGF, s = 0.f;
    for (int t = lane; t < w; t += 32)
        lse_add(m, s, Lp[t] + Rp[w - 1 - t]);
    float M, S;
    warp_lse_merge(m, s, M, S);
    float res = M + __logf(S) + __ldg(&lg[i * L + i + w]);
    if (lane == 0)      bS[i * L + w] = res;
    else if (lane == 1) bE[(i + w) * L + w] = res;
}

// -------- outside: one warp computes alpha(a, a+w); returns loss term (lane 0) --------
__device__ __forceinline__ double outside_cell(int a, int w, int n,
        const float* __restrict__ lg, const float* __restrict__ lgT,
        const float* __restrict__ bS, const float* __restrict__ bE,
        float* __restrict__ aS, float* __restrict__ aE, float logZ,
        const float* __restrict__ pharc, const int* __restrict__ spans, int lane) {
    const int bj = a + w;
    const int c1 = n - 1 - bj;          // parent-right count
    float m = NEGF, s = 0.f;
    {   // type 1: parent (a, j), j = bj+1 .. n-1  — all streams ascending contiguous
        const float* __restrict__ A1 = aS + a * L + (w + 1);
        const float* __restrict__ G1 = lg + a * L + (bj + 1);
        const float* __restrict__ B1 = bS + (bj + 1) * L;
        for (int t = lane; t < c1; t += 32)
            lse_add(m, s, A1[t] + G1[t] + B1[t]);
    }
    {   // type 2: parent (ii, bj), ii = 0 .. a-1 — descending/ascending contiguous
        const float* __restrict__ A2 = aE + bj * L + bj;       // [-ii]
        const float* __restrict__ G2 = lgT + bj * L;           // [ii]
        const float* __restrict__ B2 = bE + (a - 1) * L + (a - 1); // [-ii]
        for (int ii = lane; ii < a; ii += 32)
            lse_add(m, s, A2[-ii] + G2[ii] + B2[-ii]);
    }
    float M, S;
    warp_lse_merge(m, s, M, S);
    float alpha_v = (c1 + a > 0) ? (M + __logf(S)) : 0.f;     // root has no parents
    if (lane == 0)      aS[a * L + w] = alpha_v;
    else if (lane == 1) aE[bj * L + w] = alpha_v;
    double out = 0.0;
    if (lane == 0) {
        float mu = __expf(alpha_v + __ldg(&bS[a * L + w]) - logZ);
        mu = fminf(mu, 1.0f);
        float p  = 1.f / (1.f + __expf(-__ldg(&pharc[a * L + bj])));
        float pm = p * mu;
        out = (__ldg(&spans[a * L + bj]) >= 2) ? (double)__logf(pm) : (double)log1pf(-pm);
    }
    return out;
}

// -------- kernel A: zero accumulators --------
__global__ void zero_kernel() {
    if (threadIdx.x < 3) g_acc[threadIdx.x] = 0.0;
}

// -------- kernel B: everything (lens, transpose, inside, outside+loss, BCE) --------
__global__ void __launch_bounds__(TMAIN, 1)
main_kernel(const float* __restrict__ lg_all,
            const float* __restrict__ ph_all,  const float* __restrict__ pt_all,
            const float* __restrict__ pharc_all,
            const int* __restrict__ spans_all,
            const int* __restrict__ phind_all, const int* __restrict__ ptind_all,
            const unsigned char* __restrict__ maskspan) {
    const int b    = blockIdx.x >> 3;      // batch = cluster id
    const int rank = blockIdx.x & 7;       // CTA rank in cluster
    const int tid  = threadIdx.x;
    const int lane = tid & 31;
    const int wid  = tid >> 5;
    const int gw   = rank * 32 + wid;      // global warp id in cluster [0,256)

    __shared__ int    sh_n;
    __shared__ double sh_red[32];

    // ---- lens (dtype-robust, warp 0) ----
    if (wid == 0) {
        const unsigned char* rowb = maskspan + (size_t)b * LL2;
        int c8 = 0;
        for (int j = lane; j < L; j += 32) c8 += (rowb[j] != 0) ? 1 : 0;
        #pragma unroll
        for (int o = 16; o; o >>= 1) c8 += __shfl_xor_sync(0xffffffffu, c8, o);
        int n;
        if (c8 >= 100 && rowb[0] == 1) {
            n = c8;
        } else {
            const unsigned int* rowi = ((const unsigned int*)maskspan) + (size_t)b * LL2;
            int c32 = 0;
            for (int j = lane; j < L; j += 32) c32 += (rowi[j] != 0u) ? 1 : 0;
            #pragma unroll
            for (int o = 16; o; o >>= 1) c32 += __shfl_xor_sync(0xffffffffu, c32, o);
            n = c32;
        }
        n = max(1, min(L, n));
        if (lane == 0) {
            sh_n = n;
            if (rank == 0) g_lens[b] = n;
        }
    }
    __syncthreads();
    const int n = sh_n;

    const float* __restrict__ lg    = lg_all    + (size_t)b * LL2;
    const float* __restrict__ pharc = pharc_all + (size_t)b * LL2;
    const int*   __restrict__ spans = spans_all + (size_t)b * LL2;
    float* __restrict__ bS  = g_bS  + (size_t)b * LL2;
    float* __restrict__ bE  = g_bE  + (size_t)b * LL2;
    float* __restrict__ aS  = g_aS  + (size_t)b * LL2;
    float* __restrict__ aE  = g_aE  + (size_t)b * LL2;
    float* __restrict__ lgT = g_lgT + (size_t)b * LL2;

    // ---- transpose lg (partitioned across cluster; coalesced writes) ----
    for (int idx = rank * TMAIN + tid; idx < LL2; idx += NC * TMAIN) {
        int i = idx >> 8, j = idx & (L - 1);
        lgT[idx] = __ldg(&lg[j * L + i]);        // lgT[i][j] = lg[j][i]
    }
    // ---- width-0 diagonal (redundant, all CTAs) ----
    if (tid < n) {
        float v = __ldg(&lg[tid * L + tid]);
        bS[tid * L] = v;
        bE[tid * L] = v;
    }
    CLUSTER_SYNC();

    // ---- inside, widths 1..n-1 ----
    for (int w = 1; w < n; ++w) {
        const int ncells = n - w;
        if (ncells * w > WT) {
            if (gw < ncells) inside_cell(gw, w, lg, bS, bE, lane);
            CLUSTER_SYNC();
        } else {
            for (int i = wid; i < ncells; i += 32) inside_cell(i, w, lg, bS, bE, lane);
            __syncthreads();
        }
    }

    const float logZ = bS[0 * L + (n - 1)];   // last level redundant -> self-written

    // ---- outside, widths n-1..0, loss fused ----
    double acc = 0.0;
    for (int w = n - 1; w >= 0; --w) {
        const int ncells = n - w;
        const int T = n - 1 - w;
        if (ncells * T > WT) {
            if (gw < ncells)
                acc += outside_cell(gw, w, n, lg, lgT, bS, bE, aS, aE, logZ, pharc, spans, lane);
            CLUSTER_SYNC();
        } else {
            for (int a = wid; a < ncells; a += 32) {
                double t = outside_cell(a, w, n, lg, lgT, bS, bE, aS, aE, logZ, pharc, spans, lane);
                if (rank == 0) acc += t;       // count redundant cells exactly once
            }
            __syncthreads();
        }
    }

    // ---- BCE slice (rows of this batch, partitioned across cluster) ----
    {
        const float* __restrict__ ph    = ph_all    + (size_t)b * LL2;
        const float* __restrict__ pt    = pt_all    + (size_t)b * LL2;
        const int*   __restrict__ phind = phind_all + (size_t)b * LL2;
        const int*   __restrict__ ptind = ptind_all + (size_t)b * LL2;
        float f1 = 0.f, f2 = 0.f;
        for (int idx = rank * TMAIN + tid; idx < n * L; idx += NC * TMAIN) {
            int j = idx & (L - 1);
            if (j < n) {
                float x = __ldg(&ph[idx]);
                f1 += fmaxf(x, 0.f) + log1pf(__expf(-fabsf(x))) - x * (float)__ldg(&phind[idx]);
                float y = __ldg(&pt[idx]);
                f2 += fmaxf(y, 0.f) + log1pf(__expf(-fabsf(y))) - y * (float)__ldg(&ptind[idx]);
            }
        }
        // warp reduce floats, then CTA reduce in double
        #pragma unroll
        for (int o = 16; o; o >>= 1) {
            f1 += __shfl_down_sync(0xffffffffu, f1, o);
            f2 += __shfl_down_sync(0xffffffffu, f2, o);
        }
        __syncthreads();
        if (lane == 0) sh_red[wid] = (double)f1;
        __syncthreads();
        if (wid == 0) {
            double v = sh_red[lane];
            #pragma unroll
            for (int o = 16; o; o >>= 1) v += __shfl_down_sync(0xffffffffu, v, o);
            if (lane == 0) atomicAdd(&g_acc[1], v);
        }
        __syncthreads();
        if (lane == 0) sh_red[wid] = (double)f2;
        __syncthreads();
        if (wid == 0) {
            double v = sh_red[lane];
            #pragma unroll
            for (int o = 16; o; o >>= 1) v += __shfl_down_sync(0xffffffffu, v, o);
            if (lane == 0) atomicAdd(&g_acc[2], v);
        }
    }

    // ---- reduce span loss acc: warp -> CTA -> global atomic ----
    #pragma unroll
    for (int o = 16; o; o >>= 1) acc += __shfl_down_sync(0xffffffffu, acc, o);
    __syncthreads();
    if (lane == 0) sh_red[wid] = acc;
    __syncthreads();
    if (wid == 0) {
        double v = sh_red[lane];
        #pragma unroll
        for (int o = 16; o; o >>= 1) v += __shfl_down_sync(0xffffffffu, v, o);
        if (lane == 0) atomicAdd(&g_acc[0], v);
    }
}

// -------- kernel C: finalize --------
__global__ void final_kernel(float* __restrict__ out) {
    double lens_sum = 0.0, sq = 0.0;
    for (int bb = 0; bb < BB; ++bb) {
        double nn = (double)g_lens[bb];
        lens_sum += nn;
        sq += nn * nn;
    }
    double loss_spans = -(g_acc[0]) / lens_sum;
    double loss = 0.1 * loss_spans + 0.9 * (g_acc[1] / sq + g_acc[2] / sq);
    out[0] = (float)loss;
}

extern "C" void kernel_launch(void* const* d_in, const int* in_sizes, int n_in,
                              void* d_out, int out_size) {
    const float* span_logits = (const float*)d_in[0];
    const float* ph          = (const float*)d_in[1];
    const float* pt          = (const float*)d_in[2];
    const float* ph_arc      = (const float*)d_in[3];
    const int*   spans_ind   = (const int*)d_in[4];
    const int*   ph_ind      = (const int*)d_in[5];
    const int*   pt_ind      = (const int*)d_in[6];
    const unsigned char* maskspan = (const unsigned char*)d_in[8];

    (void)in_sizes; (void)n_in; (void)out_size;

    zero_kernel<<<1, 32>>>();

    cudaLaunchConfig_t cfg = {};
    cfg.gridDim  = dim3(BB * NC, 1, 1);
    cfg.blockDim = dim3(TMAIN, 1, 1);
    cfg.dynamicSmemBytes = 0;
    cfg.stream = 0;
    cudaLaunchAttribute attrs[1];
    attrs[0].id = cudaLaunchAttributeClusterDimension;
    attrs[0].val.clusterDim.x = NC;
    attrs[0].val.clusterDim.y = 1;
    attrs[0].val.clusterDim.z = 1;
    cfg.attrs = attrs;
    cfg.numAttrs = 1;
    cudaLaunchKernelEx(&cfg, main_kernel,
                       span_logits, ph, pt, ph_arc, spans_ind, ph_ind, pt_ind, maskspan);

    final_kernel<<<1, 1>>>((float*)d_out);
}